// round 14
// baseline (speedup 1.0000x reference)
#include <cuda_runtime.h>
#include <cuda_fp16.h>
#include <cstdint>

#define CC 64
#define KROWH 576         // padded Y row in halves: 512 y + 8 qsum + 56 zero pad
#define NKSTEP 36         // 576 / 16
#define NCHUNK2 9         // 36 / 4 ksteps per chunk

// ---------------- scratch ----------------
__device__ __half  g_Y[(size_t)50000 * KROWH];
__device__ float   g_st[(size_t)50000 * 16];
__device__ uint32_t g_Bp[NKSTEP * 4 * 32 * 4];   // fp16x2 B fragments
__device__ int     g_off[50001];

// ---------------- helpers ----------------
__device__ __forceinline__ uint32_t smem_u32(const void* p) {
    uint32_t a;
    asm("{ .reg .u64 t; cvta.to.shared.u64 t, %1; cvt.u32.u64 %0, t; }" : "=r"(a) : "l"(p));
    return a;
}
#define CPA16(s, g) asm volatile("cp.async.cg.shared.global [%0], [%1], 16;" :: "r"(s), "l"(g) : "memory")
#define CPC()       asm volatile("cp.async.commit_group;" ::: "memory")
#define CPW()       asm volatile("cp.async.wait_group 0;" ::: "memory")

__device__ __forceinline__ unsigned long long pack2(float v) {
    unsigned long long r;
    asm("mov.b64 %0, {%1, %1};" : "=l"(r) : "r"(__float_as_uint(v)));
    return r;
}
__device__ __forceinline__ unsigned long long packab(float a, float b) {
    unsigned long long r;
    asm("mov.b64 %0, {%1, %2};" : "=l"(r) : "r"(__float_as_uint(a)), "r"(__float_as_uint(b)));
    return r;
}
__device__ __forceinline__ unsigned long long fma2(unsigned long long a,
                                                   unsigned long long b,
                                                   unsigned long long c) {
    unsigned long long d;
    asm("fma.rn.f32x2 %0, %1, %2, %3;" : "=l"(d) : "l"(a), "l"(b), "l"(c));
    return d;
}
__device__ __forceinline__ void unpack2(unsigned long long v, float& lo, float& hi) {
    unsigned ulo, uhi;
    asm("mov.b64 {%0, %1}, %2;" : "=r"(ulo), "=r"(uhi) : "l"(v));
    lo = __uint_as_float(ulo);
    hi = __uint_as_float(uhi);
}

__device__ __forceinline__ void mma_f16(float* d, const unsigned* a, unsigned b0, unsigned b1) {
    asm volatile("mma.sync.aligned.m16n8k16.row.col.f32.f16.f16.f32 "
                 "{%0,%1,%2,%3}, {%4,%5,%6,%7}, {%8,%9}, {%0,%1,%2,%3};"
                 : "+f"(d[0]), "+f"(d[1]), "+f"(d[2]), "+f"(d[3])
                 : "r"(a[0]), "r"(a[1]), "r"(a[2]), "r"(a[3]), "r"(b0), "r"(b1));
}

// ---------------- kernel 1: s/t projections ----------------
__global__ void st_kernel(const float* __restrict__ x,
                          const float* __restrict__ Ws, const float* __restrict__ bs,
                          const float* __restrict__ Wt, const float* __restrict__ bt,
                          float* __restrict__ st, int n) {
    __shared__ float sW[64][16];
    __shared__ float sb[16];
    int tid = threadIdx.x; // 256
    for (int idx = tid; idx < 512; idx += 256) {
        int c = idx >> 3, k = idx & 7;
        sW[c][k]     = Ws[idx];
        sW[c][8 + k] = Wt[idx];
    }
    if (tid < 8)  sb[tid]      = bs[tid];
    else if (tid < 16) sb[tid] = bt[tid - 8];
    __syncthreads();

    int i = blockIdx.x * 256 + tid;
    if (i >= n) return;

    float acc[16];
#pragma unroll
    for (int k = 0; k < 16; k++) acc[k] = sb[k];

    const float4* x4 = (const float4*)(x + (size_t)i * CC);
#pragma unroll
    for (int c4 = 0; c4 < 16; c4++) {
        float4 xv = x4[c4];
        int c = c4 * 4;
#pragma unroll
        for (int j = 0; j < 4; j++) {
            float xc = (j == 0) ? xv.x : (j == 1) ? xv.y : (j == 2) ? xv.z : xv.w;
            const float4* wr = (const float4*)&sW[c + j][0];
            float4 w0 = wr[0], w1 = wr[1], w2 = wr[2], w3 = wr[3];
            acc[0]  = fmaf(xc, w0.x, acc[0]);  acc[1]  = fmaf(xc, w0.y, acc[1]);
            acc[2]  = fmaf(xc, w0.z, acc[2]);  acc[3]  = fmaf(xc, w0.w, acc[3]);
            acc[4]  = fmaf(xc, w1.x, acc[4]);  acc[5]  = fmaf(xc, w1.y, acc[5]);
            acc[6]  = fmaf(xc, w1.z, acc[6]);  acc[7]  = fmaf(xc, w1.w, acc[7]);
            acc[8]  = fmaf(xc, w2.x, acc[8]);  acc[9]  = fmaf(xc, w2.y, acc[9]);
            acc[10] = fmaf(xc, w2.z, acc[10]); acc[11] = fmaf(xc, w2.w, acc[11]);
            acc[12] = fmaf(xc, w3.x, acc[12]); acc[13] = fmaf(xc, w3.y, acc[13]);
            acc[14] = fmaf(xc, w3.z, acc[14]); acc[15] = fmaf(xc, w3.w, acc[15]);
        }
    }
    float4* stout = (float4*)(st + (size_t)i * 16);
#pragma unroll
    for (int q = 0; q < 4; q++)
        stout[q] = make_float4(acc[q*4], acc[q*4+1], acc[q*4+2], acc[q*4+3]);
}

// ---------------- kernel 2: segment offsets ----------------
__global__ void offsets_kernel(const int* __restrict__ dst, int* __restrict__ off,
                               int E, int n) {
    int e = blockIdx.x * blockDim.x + threadIdx.x;
    if (e >= E) return;
    int d  = dst[e];
    int dp = (e == 0) ? -1 : dst[e - 1];
    for (int j = dp + 1; j <= d; j++) off[j] = e;
    if (e == E - 1)
        for (int j = d + 1; j <= n; j++) off[j] = E;
}

// ---------------- kernel 2b: permute [W; b] into fp16 mma B-fragments ----------------
__device__ __forceinline__ float ldWb(const float* W, const float* b, int k, int n) {
    if (k < 512) return W[k * 64 + n];
    if (k < 520) return b[(k - 512) * 64 + n];
    return 0.f;
}
// u32 idx decomposition: u = idx&3, lane = (idx>>2)&31, p = (idx>>7)&3, ks = idx>>9
// nf = 2p + (u>>1), reg = u&1: value = half2(B[ks*16+2cth+reg*8][nf*8+g], B[k+1][...])
__global__ void permute_wb(const float* __restrict__ W, const float* __restrict__ b,
                           uint32_t* __restrict__ Bp) {
    int idx = blockIdx.x * 256 + threadIdx.x;
    if (idx >= NKSTEP * 4 * 32 * 4) return;
    int u    = idx & 3;
    int lane = (idx >> 2) & 31;
    int p    = (idx >> 7) & 3;
    int ks   = idx >> 9;
    int nf  = p * 2 + (u >> 1);
    int reg = u & 1;
    int g = lane >> 2, cth = lane & 3;
    int k  = ks * 16 + 2 * cth + reg * 8;
    int nn = nf * 8 + g;
    __half2 v = __floats2half2_rn(ldWb(W, b, k, nn), ldWb(W, b, k + 1, nn));
    Bp[idx] = *(uint32_t*)&v;
}

// ---------------- kernel 3: per-node edge aggregation (f32x2 packed) ----------------
__global__ void __launch_bounds__(256) edge_kernel(
        const float* __restrict__ x, const int* __restrict__ src,
        const float* __restrict__ st, const int* __restrict__ off,
        __half* __restrict__ Y, int n) {
    __shared__ unsigned long long sQp[8][16];   // packed (q_{2mp}, q_{2mp+1}) per edge b
    int gw   = (blockIdx.x * blockDim.x + threadIdx.x) >> 5;
    int lane = threadIdx.x & 31;
    int wib  = (threadIdx.x >> 5);
    if (gw >= n) return;
    int i = gw;
    int beg = off[i];
    int end = off[i + 1];

    int b = lane >> 3;     // edge within batch of 4
    int m = lane & 7;      // head

    // accp[mp][ch]: packed (head 2mp, head 2mp+1) at channel (2*lane + ch)
    unsigned long long accp[4][2];
#pragma unroll
    for (int mp = 0; mp < 4; mp++) { accp[mp][0] = 0ull; accp[mp][1] = 0ull; }
    float qs = 0.f;

    const float2* x2 = (const float2*)x;

    if (beg < end) {
        float sreg = __ldg(&st[(size_t)i * 16 + m]);

        int ee0 = beg + b; if (ee0 >= end) ee0 = end - 1;
        int   sE_n = __ldg(&src[ee0]);
        float tv_n = __ldg(&st[(size_t)sE_n * 16 + 8 + m]);

        for (int e = beg; e < end; e += 4) {
            int   sE = sE_n;
            float tv = tv_n;
            bool  valid = (e + b < end);

            int en = e + 4;
            if (en < end) {
                int eb = en + b; if (eb >= end) eb = end - 1;
                sE_n = __ldg(&src[eb]);
                tv_n = __ldg(&st[(size_t)sE_n * 16 + 8 + m]);
            }

            // hoist x-row loads ahead of softmax chain
            float2 xv[4];
#pragma unroll
            for (int b2 = 0; b2 < 4; b2++) {
                int sEb = __shfl_sync(0xffffffffu, sE, b2 * 8);
                xv[b2]  = x2[(size_t)sEb * 32 + lane];
            }

            float ex  = valid ? __expf(sreg + tv) : 0.f;
            float tot = ex;
            tot += __shfl_xor_sync(0xffffffffu, tot, 1, 8);
            tot += __shfl_xor_sync(0xffffffffu, tot, 2, 8);
            tot += __shfl_xor_sync(0xffffffffu, tot, 4, 8);
            float q = valid ? __fdividef(ex, tot) : 0.f;
            qs += q;

            // pack (q_m, q_{m+1}) from even-m lanes
            float qup = __shfl_down_sync(0xffffffffu, q, 1);
            unsigned long long pk = packab(q, qup);
            if (!(m & 1)) sQp[wib][b * 4 + (m >> 1)] = pk;
            __syncwarp();

#pragma unroll
            for (int b2 = 0; b2 < 4; b2++) {
                ulonglong2 qp01 = *(const ulonglong2*)&sQp[wib][b2 * 4];
                ulonglong2 qp23 = *(const ulonglong2*)&sQp[wib][b2 * 4 + 2];
                float2 xb = xv[b2];
                unsigned long long xpx = pack2(xb.x);
                unsigned long long xpy = pack2(xb.y);
                accp[0][0] = fma2(qp01.x, xpx, accp[0][0]);
                accp[0][1] = fma2(qp01.x, xpy, accp[0][1]);
                accp[1][0] = fma2(qp01.y, xpx, accp[1][0]);
                accp[1][1] = fma2(qp01.y, xpy, accp[1][1]);
                accp[2][0] = fma2(qp23.x, xpx, accp[2][0]);
                accp[2][1] = fma2(qp23.x, xpy, accp[2][1]);
                accp[3][0] = fma2(qp23.y, xpx, accp[3][0]);
                accp[3][1] = fma2(qp23.y, xpy, accp[3][1]);
            }
            __syncwarp();
        }

        qs += __shfl_xor_sync(0xffffffffu, qs, 8);
        qs += __shfl_xor_sync(0xffffffffu, qs, 16);
    }

    __half* Yrow = Y + (size_t)i * KROWH;
#pragma unroll
    for (int mp = 0; mp < 4; mp++) {
        float h0c0, h1c0, h0c1, h1c1;
        unpack2(accp[mp][0], h0c0, h1c0);
        unpack2(accp[mp][1], h0c1, h1c1);
        int h0 = 2 * mp, h1 = 2 * mp + 1;
        *(__half2*)(Yrow + h0 * 64 + 2 * lane) = __floats2half2_rn(h0c0, h0c1);
        *(__half2*)(Yrow + h1 * 64 + 2 * lane) = __floats2half2_rn(h1c0, h1c1);
    }
    if (lane < 8)  Yrow[512 + lane] = __float2half(qs);
    if (lane < 28) *(__half2*)(Yrow + 520 + 2 * lane) = __half2half2(__float2half(0.f));
}

// ---------------- kernel 4: fp16 mma.sync GEMM ----------------
// out[N,64] = Yh[N,576] @ B[576,64] * 0.125
// 256 thr (8 warps), block tile m=128 n=64; warp tile m16. A direct LDG (fp16),
// B fragments via cp.async double-buffered smem (4 ksteps = 8KB per chunk).
__global__ void __launch_bounds__(256) gemm_mma(const __half* __restrict__ Y,
                                                const uint32_t* __restrict__ Bp,
                                                float* __restrict__ out, int n) {
    __shared__ float4 sB[2][512];   // 2 x 8KB
    int tid  = threadIdx.x;
    int lane = tid & 31;
    int w    = tid >> 5;
    int m0   = blockIdx.x * 128;
    int g    = lane >> 2;
    int cth  = lane & 3;

    int rowA = m0 + w * 16 + g;
    int rowB = rowA + 8;
    int rAc = rowA < n ? rowA : n - 1;
    int rBc = rowB < n ? rowB : n - 1;
    const __half* YA = Y + (size_t)rAc * KROWH;
    const __half* YB = Y + (size_t)rBc * KROWH;

    float acc[8][4];
#pragma unroll
    for (int nf = 0; nf < 8; nf++)
#pragma unroll
        for (int j = 0; j < 4; j++) acc[nf][j] = 0.f;

    // prologue: B chunk 0
    {
        uint32_t sdst = smem_u32(&sB[0][tid * 2]);
        const float4* gsrc = (const float4*)Bp + tid * 2;
        CPA16(sdst, gsrc);
        CPA16(sdst + 16, gsrc + 1);
        CPC();
    }
    // prologue: A kstep 0
    unsigned areg[2][4];
    {
        int col = 2 * cth;
        areg[0][0] = *(const uint32_t*)(YA + col);
        areg[0][1] = *(const uint32_t*)(YB + col);
        areg[0][2] = *(const uint32_t*)(YA + col + 8);
        areg[0][3] = *(const uint32_t*)(YB + col + 8);
    }
    CPW();
    __syncthreads();

    for (int c = 0; c < NCHUNK2; c++) {
        int cb = c & 1;
        if (c < NCHUNK2 - 1) {
            uint32_t sdst = smem_u32(&sB[cb ^ 1][tid * 2]);
            const float4* gsrc = (const float4*)Bp + (c + 1) * 512 + tid * 2;
            CPA16(sdst, gsrc);
            CPA16(sdst + 16, gsrc + 1);
            CPC();
        }

#pragma unroll
        for (int ksl = 0; ksl < 4; ksl++) {
            int gks = c * 4 + ksl;
            int pb  = gks & 1;
            // prefetch A for next kstep
            if (gks + 1 < NKSTEP) {
                int col = (gks + 1) * 16 + 2 * cth;
                areg[pb ^ 1][0] = *(const uint32_t*)(YA + col);
                areg[pb ^ 1][1] = *(const uint32_t*)(YB + col);
                areg[pb ^ 1][2] = *(const uint32_t*)(YA + col + 8);
                areg[pb ^ 1][3] = *(const uint32_t*)(YB + col + 8);
            }

#pragma unroll
            for (int p = 0; p < 4; p++) {
                float4 bv = sB[cb][(ksl * 4 + p) * 32 + lane];
                mma_f16(acc[2 * p],     areg[pb], __float_as_uint(bv.x), __float_as_uint(bv.y));
                mma_f16(acc[2 * p + 1], areg[pb], __float_as_uint(bv.z), __float_as_uint(bv.w));
            }
        }
        CPW();
        __syncthreads();
    }

    // epilogue
#pragma unroll
    for (int nf = 0; nf < 8; nf++) {
        int col = nf * 8 + 2 * cth;
        if (rowA < n)
            *(float2*)(out + (size_t)rowA * 64 + col) =
                make_float2(acc[nf][0] * 0.125f, acc[nf][1] * 0.125f);
        if (rowB < n)
            *(float2*)(out + (size_t)rowB * 64 + col) =
                make_float2(acc[nf][2] * 0.125f, acc[nf][3] * 0.125f);
    }
}

// ---------------- launch ----------------
extern "C" void kernel_launch(void* const* d_in, const int* in_sizes, int n_in,
                              void* d_out, int out_size) {
    const float* x   = (const float*)d_in[0];
    const int*   src = (const int*)d_in[1];
    const int*   dst = (const int*)d_in[2];
    const float* W   = (const float*)d_in[3];
    const float* b   = (const float*)d_in[4];
    const float* Ws  = (const float*)d_in[5];
    const float* bs  = (const float*)d_in[6];
    const float* Wt  = (const float*)d_in[7];
    const float* bt  = (const float*)d_in[8];
    float* out = (float*)d_out;

    int n = in_sizes[0] / CC;   // 50000
    int E = in_sizes[1];        // 1700000

    __half*   Y;  cudaGetSymbolAddress((void**)&Y,  g_Y);
    float*    st; cudaGetSymbolAddress((void**)&st, g_st);
    uint32_t* Bp; cudaGetSymbolAddress((void**)&Bp, g_Bp);
    int*      off; cudaGetSymbolAddress((void**)&off, g_off);

    st_kernel<<<(n + 255) / 256, 256>>>(x, Ws, bs, Wt, bt, st, n);
    offsets_kernel<<<(E + 255) / 256, 256>>>(dst, off, E, n);
    permute_wb<<<(NKSTEP * 4 * 32 * 4 + 255) / 256, 256>>>(W, b, Bp);
    edge_kernel<<<(n * 32 + 255) / 256, 256>>>(x, src, st, off, Y, n);
    gemm_mma<<<(n + 127) / 128, 256>>>(Y, Bp, out, n);
}

// round 15
// speedup vs baseline: 1.0062x; 1.0062x over previous
#include <cuda_runtime.h>
#include <cuda_fp16.h>
#include <cstdint>

#define CC 64
#define KROWH 576         // padded Y row in halves: 512 y + 8 qsum + 56 zero pad
#define NKSTEP 36         // 576 / 16
#define NCHUNK2 9         // 36 / 4 ksteps per chunk

// ---------------- scratch ----------------
__device__ __half  g_Y[(size_t)50000 * KROWH];
__device__ float   g_st[(size_t)50000 * 16];
__device__ uint32_t g_Bp[NKSTEP * 4 * 32 * 4];   // fp16x2 B fragments
__device__ int     g_off[50001];

// ---------------- helpers ----------------
__device__ __forceinline__ uint32_t smem_u32(const void* p) {
    uint32_t a;
    asm("{ .reg .u64 t; cvta.to.shared.u64 t, %1; cvt.u32.u64 %0, t; }" : "=r"(a) : "l"(p));
    return a;
}
#define CPA16(s, g) asm volatile("cp.async.cg.shared.global [%0], [%1], 16;" :: "r"(s), "l"(g) : "memory")
#define CPC()       asm volatile("cp.async.commit_group;" ::: "memory")
#define CPW()       asm volatile("cp.async.wait_group 0;" ::: "memory")

__device__ __forceinline__ unsigned long long pack2(float v) {
    unsigned long long r;
    asm("mov.b64 %0, {%1, %1};" : "=l"(r) : "r"(__float_as_uint(v)));
    return r;
}
__device__ __forceinline__ unsigned long long packab(float a, float b) {
    unsigned long long r;
    asm("mov.b64 %0, {%1, %2};" : "=l"(r) : "r"(__float_as_uint(a)), "r"(__float_as_uint(b)));
    return r;
}
__device__ __forceinline__ unsigned long long fma2(unsigned long long a,
                                                   unsigned long long b,
                                                   unsigned long long c) {
    unsigned long long d;
    asm("fma.rn.f32x2 %0, %1, %2, %3;" : "=l"(d) : "l"(a), "l"(b), "l"(c));
    return d;
}
__device__ __forceinline__ void unpack2(unsigned long long v, float& lo, float& hi) {
    unsigned ulo, uhi;
    asm("mov.b64 {%0, %1}, %2;" : "=r"(ulo), "=r"(uhi) : "l"(v));
    lo = __uint_as_float(ulo);
    hi = __uint_as_float(uhi);
}

__device__ __forceinline__ void mma_f16(float* d, const unsigned* a, unsigned b0, unsigned b1) {
    asm volatile("mma.sync.aligned.m16n8k16.row.col.f32.f16.f16.f32 "
                 "{%0,%1,%2,%3}, {%4,%5,%6,%7}, {%8,%9}, {%0,%1,%2,%3};"
                 : "+f"(d[0]), "+f"(d[1]), "+f"(d[2]), "+f"(d[3])
                 : "r"(a[0]), "r"(a[1]), "r"(a[2]), "r"(a[3]), "r"(b0), "r"(b1));
}

// ---------------- kernel 1: s/t projections ----------------
__global__ void st_kernel(const float* __restrict__ x,
                          const float* __restrict__ Ws, const float* __restrict__ bs,
                          const float* __restrict__ Wt, const float* __restrict__ bt,
                          float* __restrict__ st, int n) {
    __shared__ float sW[64][16];
    __shared__ float sb[16];
    int tid = threadIdx.x; // 256
    for (int idx = tid; idx < 512; idx += 256) {
        int c = idx >> 3, k = idx & 7;
        sW[c][k]     = Ws[idx];
        sW[c][8 + k] = Wt[idx];
    }
    if (tid < 8)  sb[tid]      = bs[tid];
    else if (tid < 16) sb[tid] = bt[tid - 8];
    __syncthreads();

    int i = blockIdx.x * 256 + tid;
    if (i >= n) return;

    float acc[16];
#pragma unroll
    for (int k = 0; k < 16; k++) acc[k] = sb[k];

    const float4* x4 = (const float4*)(x + (size_t)i * CC);
#pragma unroll
    for (int c4 = 0; c4 < 16; c4++) {
        float4 xv = x4[c4];
        int c = c4 * 4;
#pragma unroll
        for (int j = 0; j < 4; j++) {
            float xc = (j == 0) ? xv.x : (j == 1) ? xv.y : (j == 2) ? xv.z : xv.w;
            const float4* wr = (const float4*)&sW[c + j][0];
            float4 w0 = wr[0], w1 = wr[1], w2 = wr[2], w3 = wr[3];
            acc[0]  = fmaf(xc, w0.x, acc[0]);  acc[1]  = fmaf(xc, w0.y, acc[1]);
            acc[2]  = fmaf(xc, w0.z, acc[2]);  acc[3]  = fmaf(xc, w0.w, acc[3]);
            acc[4]  = fmaf(xc, w1.x, acc[4]);  acc[5]  = fmaf(xc, w1.y, acc[5]);
            acc[6]  = fmaf(xc, w1.z, acc[6]);  acc[7]  = fmaf(xc, w1.w, acc[7]);
            acc[8]  = fmaf(xc, w2.x, acc[8]);  acc[9]  = fmaf(xc, w2.y, acc[9]);
            acc[10] = fmaf(xc, w2.z, acc[10]); acc[11] = fmaf(xc, w2.w, acc[11]);
            acc[12] = fmaf(xc, w3.x, acc[12]); acc[13] = fmaf(xc, w3.y, acc[13]);
            acc[14] = fmaf(xc, w3.z, acc[14]); acc[15] = fmaf(xc, w3.w, acc[15]);
        }
    }
    float4* stout = (float4*)(st + (size_t)i * 16);
#pragma unroll
    for (int q = 0; q < 4; q++)
        stout[q] = make_float4(acc[q*4], acc[q*4+1], acc[q*4+2], acc[q*4+3]);
}

// ---------------- kernel 2: segment offsets ----------------
__global__ void offsets_kernel(const int* __restrict__ dst, int* __restrict__ off,
                               int E, int n) {
    int e = blockIdx.x * blockDim.x + threadIdx.x;
    if (e >= E) return;
    int d  = dst[e];
    int dp = (e == 0) ? -1 : dst[e - 1];
    for (int j = dp + 1; j <= d; j++) off[j] = e;
    if (e == E - 1)
        for (int j = d + 1; j <= n; j++) off[j] = E;
}

// ---------------- kernel 2b: permute [W; b] into fp16 mma B-fragments ----------------
__device__ __forceinline__ float ldWb(const float* W, const float* b, int k, int n) {
    if (k < 512) return W[k * 64 + n];
    if (k < 520) return b[(k - 512) * 64 + n];
    return 0.f;
}
// u32 idx decomposition: u = idx&3, lane = (idx>>2)&31, p = (idx>>7)&3, ks = idx>>9
// nf = 2p + (u>>1), reg = u&1: value = half2(B[ks*16+2cth+reg*8][nf*8+g], B[k+1][...])
__global__ void permute_wb(const float* __restrict__ W, const float* __restrict__ b,
                           uint32_t* __restrict__ Bp) {
    int idx = blockIdx.x * 256 + threadIdx.x;
    if (idx >= NKSTEP * 4 * 32 * 4) return;
    int u    = idx & 3;
    int lane = (idx >> 2) & 31;
    int p    = (idx >> 7) & 3;
    int ks   = idx >> 9;
    int nf  = p * 2 + (u >> 1);
    int reg = u & 1;
    int g = lane >> 2, cth = lane & 3;
    int k  = ks * 16 + 2 * cth + reg * 8;
    int nn = nf * 8 + g;
    __half2 v = __floats2half2_rn(ldWb(W, b, k, nn), ldWb(W, b, k + 1, nn));
    Bp[idx] = *(uint32_t*)&v;
}

// ---------------- kernel 3: per-node edge aggregation (f32x2 packed) ----------------
__global__ void __launch_bounds__(256) edge_kernel(
        const float* __restrict__ x, const int* __restrict__ src,
        const float* __restrict__ st, const int* __restrict__ off,
        __half* __restrict__ Y, int n) {
    __shared__ unsigned long long sQp[8][16];   // packed (q_{2mp}, q_{2mp+1}) per edge b
    int gw   = (blockIdx.x * blockDim.x + threadIdx.x) >> 5;
    int lane = threadIdx.x & 31;
    int wib  = (threadIdx.x >> 5);
    if (gw >= n) return;
    int i = gw;
    int beg = off[i];
    int end = off[i + 1];

    int b = lane >> 3;     // edge within batch of 4
    int m = lane & 7;      // head

    // accp[mp][ch]: packed (head 2mp, head 2mp+1) at channel (2*lane + ch)
    unsigned long long accp[4][2];
#pragma unroll
    for (int mp = 0; mp < 4; mp++) { accp[mp][0] = 0ull; accp[mp][1] = 0ull; }
    float qs = 0.f;

    const float2* x2 = (const float2*)x;

    if (beg < end) {
        float sreg = __ldg(&st[(size_t)i * 16 + m]);

        int ee0 = beg + b; if (ee0 >= end) ee0 = end - 1;
        int   sE_n = __ldg(&src[ee0]);
        float tv_n = __ldg(&st[(size_t)sE_n * 16 + 8 + m]);

        for (int e = beg; e < end; e += 4) {
            int   sE = sE_n;
            float tv = tv_n;
            bool  valid = (e + b < end);

            int en = e + 4;
            if (en < end) {
                int eb = en + b; if (eb >= end) eb = end - 1;
                sE_n = __ldg(&src[eb]);
                tv_n = __ldg(&st[(size_t)sE_n * 16 + 8 + m]);
            }

            // hoist x-row loads ahead of softmax chain
            float2 xv[4];
#pragma unroll
            for (int b2 = 0; b2 < 4; b2++) {
                int sEb = __shfl_sync(0xffffffffu, sE, b2 * 8);
                xv[b2]  = x2[(size_t)sEb * 32 + lane];
            }

            float ex  = valid ? __expf(sreg + tv) : 0.f;
            float tot = ex;
            tot += __shfl_xor_sync(0xffffffffu, tot, 1, 8);
            tot += __shfl_xor_sync(0xffffffffu, tot, 2, 8);
            tot += __shfl_xor_sync(0xffffffffu, tot, 4, 8);
            float q = valid ? __fdividef(ex, tot) : 0.f;
            qs += q;

            // pack (q_m, q_{m+1}) from even-m lanes
            float qup = __shfl_down_sync(0xffffffffu, q, 1);
            unsigned long long pk = packab(q, qup);
            if (!(m & 1)) sQp[wib][b * 4 + (m >> 1)] = pk;
            __syncwarp();

#pragma unroll
            for (int b2 = 0; b2 < 4; b2++) {
                ulonglong2 qp01 = *(const ulonglong2*)&sQp[wib][b2 * 4];
                ulonglong2 qp23 = *(const ulonglong2*)&sQp[wib][b2 * 4 + 2];
                float2 xb = xv[b2];
                unsigned long long xpx = pack2(xb.x);
                unsigned long long xpy = pack2(xb.y);
                accp[0][0] = fma2(qp01.x, xpx, accp[0][0]);
                accp[0][1] = fma2(qp01.x, xpy, accp[0][1]);
                accp[1][0] = fma2(qp01.y, xpx, accp[1][0]);
                accp[1][1] = fma2(qp01.y, xpy, accp[1][1]);
                accp[2][0] = fma2(qp23.x, xpx, accp[2][0]);
                accp[2][1] = fma2(qp23.x, xpy, accp[2][1]);
                accp[3][0] = fma2(qp23.y, xpx, accp[3][0]);
                accp[3][1] = fma2(qp23.y, xpy, accp[3][1]);
            }
            __syncwarp();
        }

        qs += __shfl_xor_sync(0xffffffffu, qs, 8);
        qs += __shfl_xor_sync(0xffffffffu, qs, 16);
    }

    __half* Yrow = Y + (size_t)i * KROWH;
#pragma unroll
    for (int mp = 0; mp < 4; mp++) {
        float h0c0, h1c0, h0c1, h1c1;
        unpack2(accp[mp][0], h0c0, h1c0);
        unpack2(accp[mp][1], h0c1, h1c1);
        int h0 = 2 * mp, h1 = 2 * mp + 1;
        *(__half2*)(Yrow + h0 * 64 + 2 * lane) = __floats2half2_rn(h0c0, h0c1);
        *(__half2*)(Yrow + h1 * 64 + 2 * lane) = __floats2half2_rn(h1c0, h1c1);
    }
    if (lane < 8)  Yrow[512 + lane] = __float2half(qs);
    if (lane < 28) *(__half2*)(Yrow + 520 + 2 * lane) = __half2half2(__float2half(0.f));
}

// ---------------- kernel 4: fp16 mma.sync GEMM ----------------
// out[N,64] = Yh[N,576] @ B[576,64] * 0.125
// 256 thr (8 warps), block tile m=128 n=64; warp tile m16. A direct LDG (fp16),
// B fragments via cp.async double-buffered smem (4 ksteps = 8KB per chunk).
__global__ void __launch_bounds__(256) gemm_mma(const __half* __restrict__ Y,
                                                const uint32_t* __restrict__ Bp,
                                                float* __restrict__ out, int n) {
    __shared__ float4 sB[2][512];   // 2 x 8KB
    int tid  = threadIdx.x;
    int lane = tid & 31;
    int w    = tid >> 5;
    int m0   = blockIdx.x * 128;
    int g    = lane >> 2;
    int cth  = lane & 3;

    int rowA = m0 + w * 16 + g;
    int rowB = rowA + 8;
    int rAc = rowA < n ? rowA : n - 1;
    int rBc = rowB < n ? rowB : n - 1;
    const __half* YA = Y + (size_t)rAc * KROWH;
    const __half* YB = Y + (size_t)rBc * KROWH;

    float acc[8][4];
#pragma unroll
    for (int nf = 0; nf < 8; nf++)
#pragma unroll
        for (int j = 0; j < 4; j++) acc[nf][j] = 0.f;

    // prologue: B chunk 0
    {
        uint32_t sdst = smem_u32(&sB[0][tid * 2]);
        const float4* gsrc = (const float4*)Bp + tid * 2;
        CPA16(sdst, gsrc);
        CPA16(sdst + 16, gsrc + 1);
        CPC();
    }
    // prologue: A kstep 0
    unsigned areg[2][4];
    {
        int col = 2 * cth;
        areg[0][0] = *(const uint32_t*)(YA + col);
        areg[0][1] = *(const uint32_t*)(YB + col);
        areg[0][2] = *(const uint32_t*)(YA + col + 8);
        areg[0][3] = *(const uint32_t*)(YB + col + 8);
    }
    CPW();
    __syncthreads();

    for (int c = 0; c < NCHUNK2; c++) {
        int cb = c & 1;
        if (c < NCHUNK2 - 1) {
            uint32_t sdst = smem_u32(&sB[cb ^ 1][tid * 2]);
            const float4* gsrc = (const float4*)Bp + (c + 1) * 512 + tid * 2;
            CPA16(sdst, gsrc);
            CPA16(sdst + 16, gsrc + 1);
            CPC();
        }

#pragma unroll
        for (int ksl = 0; ksl < 4; ksl++) {
            int gks = c * 4 + ksl;
            int pb  = gks & 1;
            // prefetch A for next kstep
            if (gks + 1 < NKSTEP) {
                int col = (gks + 1) * 16 + 2 * cth;
                areg[pb ^ 1][0] = *(const uint32_t*)(YA + col);
                areg[pb ^ 1][1] = *(const uint32_t*)(YB + col);
                areg[pb ^ 1][2] = *(const uint32_t*)(YA + col + 8);
                areg[pb ^ 1][3] = *(const uint32_t*)(YB + col + 8);
            }

#pragma unroll
            for (int p = 0; p < 4; p++) {
                float4 bv = sB[cb][(ksl * 4 + p) * 32 + lane];
                mma_f16(acc[2 * p],     areg[pb], __float_as_uint(bv.x), __float_as_uint(bv.y));
                mma_f16(acc[2 * p + 1], areg[pb], __float_as_uint(bv.z), __float_as_uint(bv.w));
            }
        }
        CPW();
        __syncthreads();
    }

    // epilogue
#pragma unroll
    for (int nf = 0; nf < 8; nf++) {
        int col = nf * 8 + 2 * cth;
        if (rowA < n)
            *(float2*)(out + (size_t)rowA * 64 + col) =
                make_float2(acc[nf][0] * 0.125f, acc[nf][1] * 0.125f);
        if (rowB < n)
            *(float2*)(out + (size_t)rowB * 64 + col) =
                make_float2(acc[nf][2] * 0.125f, acc[nf][3] * 0.125f);
    }
}

// ---------------- launch ----------------
extern "C" void kernel_launch(void* const* d_in, const int* in_sizes, int n_in,
                              void* d_out, int out_size) {
    const float* x   = (const float*)d_in[0];
    const int*   src = (const int*)d_in[1];
    const int*   dst = (const int*)d_in[2];
    const float* W   = (const float*)d_in[3];
    const float* b   = (const float*)d_in[4];
    const float* Ws  = (const float*)d_in[5];
    const float* bs  = (const float*)d_in[6];
    const float* Wt  = (const float*)d_in[7];
    const float* bt  = (const float*)d_in[8];
    float* out = (float*)d_out;

    int n = in_sizes[0] / CC;   // 50000
    int E = in_sizes[1];        // 1700000

    __half*   Y;  cudaGetSymbolAddress((void**)&Y,  g_Y);
    float*    st; cudaGetSymbolAddress((void**)&st, g_st);
    uint32_t* Bp; cudaGetSymbolAddress((void**)&Bp, g_Bp);
    int*      off; cudaGetSymbolAddress((void**)&off, g_off);

    st_kernel<<<(n + 255) / 256, 256>>>(x, Ws, bs, Wt, bt, st, n);
    offsets_kernel<<<(E + 255) / 256, 256>>>(dst, off, E, n);
    permute_wb<<<(NKSTEP * 4 * 32 * 4 + 255) / 256, 256>>>(W, b, Bp);
    edge_kernel<<<(n * 32 + 255) / 256, 256>>>(x, src, st, off, Y, n);
    gemm_mma<<<(n + 127) / 128, 256>>>(Y, Bp, out, n);
}